// round 7
// baseline (speedup 1.0000x reference)
#include <cuda_runtime.h>
#include <cuda_fp16.h>
#include <math_constants.h>
#include <cstdint>

#define NB    16
#define CDIM  256
#define NPIX  4096
#define SPLITK 4
#define NROWS (NB * 512)          // 8192 k rows
#define NTILES_K1 16              // NPIX / 256

// ---------------------------------------------------------------------------
// scratch (device globals; allocation-free per harness rules)
// ---------------------------------------------------------------------------
__device__ __align__(16) __half g_xThi[(size_t)NB * NPIX * CDIM];   // xT[b][n][c] fp16
__device__ __align__(16) __half g_vhi [(size_t)NB * 512 * NPIX];
__device__ __align__(16) __half g_ekhi[(size_t)NB * 512 * NPIX];    // exp(k), no max shift
__device__ float g_partsum[(size_t)NTILES_K1 * NROWS];              // per-ntile row sums
__device__ __align__(16) float g_part[(size_t)SPLITK * 64 * 128 * 128];
__device__ __align__(16) float g_ctxT[(size_t)64 * 128 * 128];
__device__ __align__(16) float g_W2[NB * 256 * 512];
__device__ __align__(16) float g_W3[NB * 256 * 256];
__device__ __align__(16) __half g_wkvhi[1024 * 256];
__device__ __align__(16) __half g_W3hi[NB * 256 * 256];

// ---------------------------------------------------------------------------
// helpers
// ---------------------------------------------------------------------------
__device__ __forceinline__ uint32_t smem_to_u32(const void* p) {
    uint32_t a;
    asm("{ .reg .u64 t; cvta.to.shared.u64 t, %1; cvt.u32.u64 %0, t; }" : "=r"(a) : "l"(p));
    return a;
}

#define LDMATRIX_X4(r, addr) \
    asm volatile("ldmatrix.sync.aligned.m8n8.x4.shared.b16 {%0,%1,%2,%3}, [%4];" \
        : "=r"((r)[0]), "=r"((r)[1]), "=r"((r)[2]), "=r"((r)[3]) : "r"(addr))

#define MMA_F16(d, a, b) \
    asm volatile("mma.sync.aligned.m16n8k16.row.col.f32.f16.f16.f32 " \
        "{%0,%1,%2,%3},{%4,%5,%6,%7},{%8,%9},{%0,%1,%2,%3};" \
        : "+f"((d)[0]), "+f"((d)[1]), "+f"((d)[2]), "+f"((d)[3]) \
        : "r"((a)[0]), "r"((a)[1]), "r"((a)[2]), "r"((a)[3]), \
          "r"((b)[0]), "r"((b)[1]))

#define CP_ASYNC16(saddr, gaddr) \
    asm volatile("cp.async.cg.shared.global [%0], [%1], 16;" :: "r"(saddr), "l"(gaddr))
#define CP_COMMIT()  asm volatile("cp.async.commit_group;")
#define CP_WAIT2()   asm volatile("cp.async.wait_group 2;")
#define CP_WAIT1()   asm volatile("cp.async.wait_group 1;")
#define CP_WAIT0()   asm volatile("cp.async.wait_group 0;")

// ===========================================================================
// BIG-TILE GEMM: 128(M) x 256(N), BK=64, 8 warps (2x4), warp tile 64x64.
// D = A[128,K] x B[256,K]^T, fp32 accum, 3-stage cp.async.
// OUTMODE 0: fp32 out (+ optional bias).
// OUTMODE 1 (K1): m0<512 -> ek = exp(acc) fp16 + per-row partial sums;
//                 m0>=512 -> v fp16.
// smem stage: A 16KB @0, B 32KB @16K; stage stride 48KB.
// ===========================================================================
__device__ __forceinline__ void load_stage_big(
    const __half* __restrict__ gA, int lda,
    const __half* __restrict__ gB, int ldb,
    uint32_t sb, int tid, int st, int kb)
{
    uint32_t base = sb + st * 49152;
    #pragma unroll
    for (int t = 0; t < 12; t++) {
        int i = tid + t * 256;
        const __half* g;
        uint32_t soff;
        if (i < 1024) {
            int row = i >> 3, seg = i & 7;
            g = gA + (size_t)row * lda + kb + seg * 8;
            uint32_t off = (row << 7) + (seg << 4);
            off ^= (row & 7) << 4;
            soff = off;
        } else {
            int idx = i - 1024;
            int row = idx >> 3, seg = idx & 7;
            g = gB + (size_t)row * ldb + kb + seg * 8;
            uint32_t off = (row << 7) + (seg << 4);
            off ^= (row & 7) << 4;
            soff = 16384 + off;
        }
        CP_ASYNC16(base + soff, g);
    }
    CP_COMMIT();
}

template <int OUTMODE>
__global__ __launch_bounds__(256, 1) void mma_gemm_big(
    const __half* __restrict__ A, const __half* __restrict__ B,
    float* __restrict__ C, __half* __restrict__ Cek, __half* __restrict__ Cv,
    float* __restrict__ partsum, const float* __restrict__ bias,
    int Ksub, int lda, int ldb, int ldc,
    long sAz, long sBz, long sCz)
{
    extern __shared__ __align__(128) char smem[];
    uint32_t sb = smem_to_u32(smem);
    const int tid = threadIdx.x, lane = tid & 31, wid = tid >> 5;
    const int wm = wid >> 2, wn = wid & 3;      // 2 x 4 warp grid

    const int ntile = blockIdx.x;               // 256-wide N tiles
    const int m0 = blockIdx.y * 128;
    const int z  = blockIdx.z;

    const __half* gA = A + z * sAz + (long)m0 * lda;
    const __half* gB = B + z * sBz + (long)ntile * 256 * ldb;

    float acc[4][8][4];
    #pragma unroll
    for (int i = 0; i < 4; i++)
        #pragma unroll
        for (int j = 0; j < 8; j++)
            #pragma unroll
            for (int q = 0; q < 4; q++) acc[i][j][q] = 0.0f;

    const int nch = Ksub >> 6;
    load_stage_big(gA, lda, gB, ldb, sb, tid, 0, 0);
    if (nch > 1) load_stage_big(gA, lda, gB, ldb, sb, tid, 1, 64);

    for (int c = 0; c < nch; c++) {
        const int st = c % 3;
        if (c + 2 < nch) { load_stage_big(gA, lda, gB, ldb, sb, tid, (c + 2) % 3, (c + 2) << 6); CP_WAIT2(); }
        else if (c + 1 < nch) { CP_WAIT1(); }
        else { CP_WAIT0(); }
        __syncthreads();

        const uint32_t sA = sb + st * 49152;
        const uint32_t sB = sA + 16384;

        #pragma unroll
        for (int s = 0; s < 4; s++) {
            uint32_t ah[4][4];
            #pragma unroll
            for (int mt = 0; mt < 4; mt++) {
                int row = wm * 64 + mt * 16 + (lane & 15);
                uint32_t off = (row << 7) + s * 32 + ((lane >> 4) << 4);
                off ^= (row & 7) << 4;
                LDMATRIX_X4(ah[mt], sA + off);
            }
            uint32_t bh[4][4];
            #pragma unroll
            for (int np = 0; np < 4; np++) {
                int nrow = wn * 64 + np * 16 + ((lane >> 4) << 3) + (lane & 7);
                uint32_t off = (nrow << 7) + s * 32 + (((lane >> 3) & 1) << 4);
                off ^= (nrow & 7) << 4;
                LDMATRIX_X4(bh[np], sB + off);
            }
            #pragma unroll
            for (int mt = 0; mt < 4; mt++)
                #pragma unroll
                for (int nt = 0; nt < 8; nt++)
                    MMA_F16(acc[mt][nt], ah[mt], &bh[nt >> 1][(nt & 1) * 2]);
        }
        __syncthreads();
    }

    // -------- epilogue --------
    const int rbase = wm * 64 + (lane >> 2);
    const int cbase = wn * 64 + (lane & 3) * 2;

    if (OUTMODE == 0) {
        float* Cw = C + z * sCz + (long)m0 * ldc + (long)ntile * 256;
        #pragma unroll
        for (int mt = 0; mt < 4; mt++)
            #pragma unroll
            for (int nt = 0; nt < 8; nt++)
                #pragma unroll
                for (int hh = 0; hh < 2; hh++) {
                    int row = rbase + mt * 16 + hh * 8;
                    int col = cbase + nt * 8;
                    float v0 = acc[mt][nt][hh * 2 + 0];
                    float v1 = acc[mt][nt][hh * 2 + 1];
                    if (bias) { float bv = bias[m0 + row]; v0 += bv; v1 += bv; }
                    *(float2*)&Cw[(long)row * ldc + col] = make_float2(v0, v1);
                }
    } else if (m0 < 512) {
        // k rows: exp (no max shift; k ~ N(0,1), fp16 range safe),
        // store fp16, per-row partial sums -> deterministic partsum write
        __half* ek = Cek + (long)z * sCz + (long)m0 * ldc + (long)ntile * 256;
        float rs[4][2];
        #pragma unroll
        for (int mt = 0; mt < 4; mt++) { rs[mt][0] = 0.f; rs[mt][1] = 0.f; }
        #pragma unroll
        for (int mt = 0; mt < 4; mt++)
            #pragma unroll
            for (int nt = 0; nt < 8; nt++)
                #pragma unroll
                for (int hh = 0; hh < 2; hh++) {
                    int row = rbase + mt * 16 + hh * 8;
                    int col = cbase + nt * 8;
                    float e0 = __expf(acc[mt][nt][hh * 2 + 0]);
                    float e1 = __expf(acc[mt][nt][hh * 2 + 1]);
                    __half2 p; p.x = __float2half_rn(e0); p.y = __float2half_rn(e1);
                    *(__half2*)&ek[(long)row * ldc + col] = p;
                    rs[mt][hh] += e0 + e1;
                }
        float* red = (float*)smem;   // 4 warps-in-N x 128 rows (MMA loop drained)
        #pragma unroll
        for (int mt = 0; mt < 4; mt++)
            #pragma unroll
            for (int hh = 0; hh < 2; hh++) {
                float v = rs[mt][hh];
                v += __shfl_xor_sync(0xffffffffu, v, 1);
                v += __shfl_xor_sync(0xffffffffu, v, 2);
                if ((lane & 3) == 0)
                    red[wn * 128 + wm * 64 + mt * 16 + hh * 8 + (lane >> 2)] = v;
            }
        __syncthreads();
        if (tid < 128)
            partsum[(long)ntile * NROWS + (long)z * 512 + m0 + tid] =
                (red[tid] + red[128 + tid]) + (red[256 + tid] + red[384 + tid]);
    } else {
        // v rows: fp16 store
        __half* vout = Cv + (long)z * sCz + (long)(m0 - 512) * ldc + (long)ntile * 256;
        #pragma unroll
        for (int mt = 0; mt < 4; mt++)
            #pragma unroll
            for (int nt = 0; nt < 8; nt++)
                #pragma unroll
                for (int hh = 0; hh < 2; hh++) {
                    int row = rbase + mt * 16 + hh * 8;
                    int col = cbase + nt * 8;
                    __half2 p;
                    p.x = __float2half_rn(acc[mt][nt][hh * 2 + 0]);
                    p.y = __float2half_rn(acc[mt][nt][hh * 2 + 1]);
                    *(__half2*)&vout[(long)row * ldc + col] = p;
                }
    }
}

// ===========================================================================
// SMALL GEMM (K3 split-K only): 128x128, BK=64, 8 warps (4x2), warp 32x64.
// ===========================================================================
__device__ __forceinline__ void load_stage_small(
    const __half* __restrict__ gA, int lda,
    const __half* __restrict__ gB, int ldb,
    uint32_t sb, int tid, int st, int kb)
{
    uint32_t base = sb + st * 32768;
    #pragma unroll
    for (int t = 0; t < 8; t++) {
        int i = tid + t * 256;
        int tile = i >> 10, idx = i & 1023, row = idx >> 3, seg = idx & 7;
        const __half* g = (tile == 0 ? gA + (size_t)row * lda : gB + (size_t)row * ldb) + kb + seg * 8;
        uint32_t off = (row << 7) + (seg << 4);
        off ^= (row & 7) << 4;
        CP_ASYNC16(base + tile * 16384 + off, g);
    }
    CP_COMMIT();
}

__global__ __launch_bounds__(256, 2) void mma_gemm_small(
    const __half* __restrict__ A, const __half* __restrict__ B,
    float* __restrict__ C,
    int Ksub, int lda, int ldb, int ldc,
    long sAz, long sBz, long sCz, long sCsplit)
{
    extern __shared__ __align__(128) char smem[];
    uint32_t sb = smem_to_u32(smem);
    const int tid = threadIdx.x, lane = tid & 31, wid = tid >> 5;
    const int wm = wid >> 1, wn = wid & 1;

    const int koff = blockIdx.x * Ksub;
    const long coff = (long)blockIdx.x * sCsplit;
    const int z = blockIdx.z;

    const __half* gA = A + z * sAz + koff;
    const __half* gB = B + z * sBz + koff;

    float acc[2][8][4];
    #pragma unroll
    for (int i = 0; i < 2; i++)
        #pragma unroll
        for (int j = 0; j < 8; j++)
            #pragma unroll
            for (int q = 0; q < 4; q++) acc[i][j][q] = 0.0f;

    const int nch = Ksub >> 6;
    load_stage_small(gA, lda, gB, ldb, sb, tid, 0, 0);
    if (nch > 1) load_stage_small(gA, lda, gB, ldb, sb, tid, 1, 64);

    for (int c = 0; c < nch; c++) {
        const int st = c % 3;
        if (c + 2 < nch) { load_stage_small(gA, lda, gB, ldb, sb, tid, (c + 2) % 3, (c + 2) << 6); CP_WAIT2(); }
        else if (c + 1 < nch) { CP_WAIT1(); }
        else { CP_WAIT0(); }
        __syncthreads();

        const uint32_t sA = sb + st * 32768;

        #pragma unroll
        for (int s = 0; s < 4; s++) {
            uint32_t ah[2][4];
            #pragma unroll
            for (int mt = 0; mt < 2; mt++) {
                int row = wm * 32 + mt * 16 + (lane & 15);
                uint32_t off = (row << 7) + s * 32 + ((lane >> 4) << 4);
                off ^= (row & 7) << 4;
                LDMATRIX_X4(ah[mt], sA + off);
            }
            uint32_t bh[4][4];
            #pragma unroll
            for (int np = 0; np < 4; np++) {
                int nrow = wn * 64 + np * 16 + ((lane >> 4) << 3) + (lane & 7);
                uint32_t off = (nrow << 7) + s * 32 + (((lane >> 3) & 1) << 4);
                off ^= (nrow & 7) << 4;
                LDMATRIX_X4(bh[np], sA + 16384 + off);
            }
            #pragma unroll
            for (int mt = 0; mt < 2; mt++)
                #pragma unroll
                for (int nt = 0; nt < 8; nt++)
                    MMA_F16(acc[mt][nt], ah[mt], &bh[nt >> 1][(nt & 1) * 2]);
        }
        __syncthreads();
    }

    float* Cw = C + z * sCz + coff;
    const int rbase = wm * 32 + (lane >> 2);
    const int cbase = wn * 64 + (lane & 3) * 2;
    #pragma unroll
    for (int mt = 0; mt < 2; mt++)
        #pragma unroll
        for (int nt = 0; nt < 8; nt++)
            #pragma unroll
            for (int hh = 0; hh < 2; hh++) {
                int row = rbase + mt * 16 + hh * 8;
                int col = cbase + nt * 8;
                *(float2*)&Cw[(long)row * ldc + col] =
                    make_float2(acc[mt][nt][hh * 2 + 0], acc[mt][nt][hh * 2 + 1]);
            }
}

// ---------------------------------------------------------------------------
// x[b][c][n] -> xT[b][n][c] as fp16
// ---------------------------------------------------------------------------
__global__ __launch_bounds__(256) void transpose_kernel(const float* __restrict__ x)
{
    __shared__ float t[32][33];
    int b = blockIdx.z, c0 = blockIdx.y * 32, n0 = blockIdx.x * 32;
    const float* xp = x + ((size_t)b * CDIM + c0) * NPIX + n0;
    int cn = threadIdx.x & 31, rr = threadIdx.x >> 5;
    #pragma unroll
    for (int i = 0; i < 4; i++) {
        int c = rr + i * 8;
        t[c][cn] = xp[(size_t)c * NPIX + cn];
    }
    __syncthreads();
    size_t ob = ((size_t)b * NPIX + n0) * CDIM + c0;
    #pragma unroll
    for (int i = 0; i < 4; i++) {
        int n = rr + i * 8;
        g_xThi[ob + (size_t)n * CDIM + cn] = __float2half_rn(t[cn][n]);
    }
}

// fp32 -> fp16, vectorized (n4 = count/4)
__global__ __launch_bounds__(256) void cvt_hi_kernel(
    const float* __restrict__ src, __half* __restrict__ hi, int n4)
{
    int i = blockIdx.x * 256 + threadIdx.x;
    if (i >= n4) return;
    float4 v = ((const float4*)src)[i];
    __half2 a, b;
    a.x = __float2half_rn(v.x); a.y = __float2half_rn(v.y);
    b.x = __float2half_rn(v.z); b.y = __float2half_rn(v.w);
    ((__half2*)hi)[i * 2 + 0] = a;
    ((__half2*)hi)[i * 2 + 1] = b;
}

// ---------------------------------------------------------------------------
// reduce split-K partials, normalize by sum-exp (computed inline from the 16
// per-ntile partials, fixed order -> deterministic), write ctxT[bh][e][d]
// ---------------------------------------------------------------------------
__global__ __launch_bounds__(256) void ctx_reduce_kernel()
{
    __shared__ float sden[2];
    int bh = blockIdx.y;
    int b = bh >> 2, h = bh & 3;
    if (threadIdx.x < 2) {
        int d = blockIdx.x * 2 + threadIdx.x;
        int row = b * 512 + h * 128 + d;
        float s = 0.0f;
        #pragma unroll
        for (int nt = 0; nt < NTILES_K1; nt++)
            s += g_partsum[(long)nt * NROWS + row];
        sden[threadIdx.x] = s;
    }
    __syncthreads();

    int idx = blockIdx.x * 256 + threadIdx.x;   // 0..16383
    int d = idx >> 7, e = idx & 127;
    float s = 0.0f;
    #pragma unroll
    for (int sp = 0; sp < SPLITK; sp++)
        s += g_part[((size_t)sp * 64 + bh) * 16384 + idx];
    float denom = sden[d & 1];
    g_ctxT[(size_t)bh * 16384 + e * 128 + d] = s / denom;
}

// ---------------------------------------------------------------------------
// small SIMT SGEMM (K4a / K4b only)
// ---------------------------------------------------------------------------
__global__ __launch_bounds__(256) void sgemm_nn(
    const float* __restrict__ A, const float* __restrict__ B,
    float* __restrict__ C, const float* __restrict__ bias,
    int M, int N, int K, int lda, int ldb, int ldc,
    int zDiv, long sAb, long sAh, long sBb, long sBh, long sCb, long sCh)
{
    __shared__ float As[16][128];
    __shared__ float Bs[16][128];

    int z  = blockIdx.z;
    int zb = z / zDiv, zh = z - zb * zDiv;
    A += zb * sAb + zh * sAh;
    B += zb * sBb + zh * sBh;
    C += zb * sCb + zh * sCh;

    int tid = threadIdx.x;
    int bm = blockIdx.y * 128;
    int bn = blockIdx.x * 128;

    int arow = tid >> 2;
    int acol = (tid & 3) * 4;
    int brow = tid >> 5;
    int bcol = (tid & 31) * 4;
    int trow = (tid >> 4) * 8;
    int tcol = (tid & 15) * 8;

    float acc[8][8];
    #pragma unroll
    for (int i = 0; i < 8; i++)
        #pragma unroll
        for (int j = 0; j < 8; j++) acc[i][j] = 0.0f;

    for (int k0 = 0; k0 < K; k0 += 16) {
        #pragma unroll
        for (int i = 0; i < 2; i++) {
            int r = arow + i * 64;
            float4 a = *(const float4*)&A[(long)(bm + r) * lda + k0 + acol];
            As[acol + 0][r] = a.x; As[acol + 1][r] = a.y;
            As[acol + 2][r] = a.z; As[acol + 3][r] = a.w;
        }
        #pragma unroll
        for (int i = 0; i < 2; i++) {
            int r = brow + i * 8;
            *(float4*)&Bs[r][bcol] = *(const float4*)&B[(long)(k0 + r) * ldb + bn + bcol];
        }
        __syncthreads();
        #pragma unroll
        for (int kk = 0; kk < 16; kk++) {
            float ra[8], rb[8];
            #pragma unroll
            for (int i = 0; i < 8; i++) ra[i] = As[kk][trow + i];
            #pragma unroll
            for (int j = 0; j < 8; j++) rb[j] = Bs[kk][tcol + j];
            #pragma unroll
            for (int i = 0; i < 8; i++)
                #pragma unroll
                for (int j = 0; j < 8; j++) acc[i][j] += ra[i] * rb[j];
        }
        __syncthreads();
    }

    #pragma unroll
    for (int i = 0; i < 8; i++) {
        long r = bm + trow + i;
        float bv = bias ? bias[r] : 0.0f;
        #pragma unroll
        for (int j = 0; j < 8; j += 4) {
            float4 o;
            o.x = acc[i][j+0] + bv; o.y = acc[i][j+1] + bv;
            o.z = acc[i][j+2] + bv; o.w = acc[i][j+3] + bv;
            *(float4*)&C[r * ldc + bn + tcol + j] = o;
        }
    }
}

// ---------------------------------------------------------------------------
extern "C" void kernel_launch(void* const* d_in, const int* in_sizes, int n_in,
                              void* d_out, int out_size)
{
    const float* x     = (const float*)d_in[0];
    const float* w_qkv = (const float*)d_in[1];
    const float* w_out = (const float*)d_in[2];
    const float* b_out = (const float*)d_in[3];
    float* y = (float*)d_out;

    float *p_part, *p_ctxT, *p_W2, *p_W3, *p_partsum;
    __half *p_xThi, *p_vhi, *p_ekhi, *p_wkvhi, *p_W3hi;
    cudaGetSymbolAddress((void**)&p_part, g_part);
    cudaGetSymbolAddress((void**)&p_ctxT, g_ctxT);
    cudaGetSymbolAddress((void**)&p_W2, g_W2);
    cudaGetSymbolAddress((void**)&p_W3, g_W3);
    cudaGetSymbolAddress((void**)&p_partsum, g_partsum);
    cudaGetSymbolAddress((void**)&p_xThi, g_xThi);
    cudaGetSymbolAddress((void**)&p_vhi, g_vhi);
    cudaGetSymbolAddress((void**)&p_ekhi, g_ekhi);
    cudaGetSymbolAddress((void**)&p_wkvhi, g_wkvhi);
    cudaGetSymbolAddress((void**)&p_W3hi, g_W3hi);

    const int SMEM_BIG   = 3 * 49152;   // 144 KB, 3 stages
    const int SMEM_SMALL = 3 * 32768;   // 96 KB, 3 stages
    cudaFuncSetAttribute(mma_gemm_big<0>, cudaFuncAttributeMaxDynamicSharedMemorySize, SMEM_BIG);
    cudaFuncSetAttribute(mma_gemm_big<1>, cudaFuncAttributeMaxDynamicSharedMemorySize, SMEM_BIG);
    cudaFuncSetAttribute(mma_gemm_small, cudaFuncAttributeMaxDynamicSharedMemorySize, SMEM_SMALL);

    dim3 t(256);

    // 1) x -> xT (fp16)
    transpose_kernel<<<dim3(NPIX / 32, CDIM / 32, NB), t>>>(x);

    // 2) Wkv -> fp16  (rows 512..1535 of w_qkv)
    cvt_hi_kernel<<<256, t>>>(w_qkv + 512 * 256, p_wkvhi, 1024 * 256 / 4);

    // 3) K1: kv = Wkv @ x; epilogue: ek = exp(k) fp16 + row partial sums, v fp16
    mma_gemm_big<1><<<dim3(NTILES_K1, 8, NB), t, SMEM_BIG>>>(
        p_wkvhi, p_xThi,
        nullptr, p_ekhi, p_vhi, p_partsum, nullptr,
        256, 256, 256, NPIX,
        0L, (long)NPIX * CDIM, 512L * NPIX);

    // 4) K3: ctx partials = ek @ v^T (split-K over n)
    mma_gemm_small<<<dim3(SPLITK, 1, 64), t, SMEM_SMALL>>>(
        p_ekhi, p_vhi, p_part,
        NPIX / SPLITK, NPIX, NPIX, 128,
        128L * NPIX, 128L * NPIX, 16384L, 64L * 16384);

    // 5) reduce + normalize (sum-exp inline) -> ctxT
    ctx_reduce_kernel<<<dim3(64, 64), t>>>();

    // 6) K4a: W2[b][o][h*128+d] = sum_e w_out[o,h*128+e] * ctxT[bh][e][d]
    sgemm_nn<<<dim3(1, 2, 64), t>>>(
        w_out, p_ctxT, p_W2, nullptr,
        256, 128, 128, 512, 128, 512,
        4, 0L, 128L, (long)4 * 16384, 16384L, (long)256 * 512, 128L);

    // 7) K4b: W3[b] = W2[b] @ Wq
    sgemm_nn<<<dim3(2, 2, NB), t>>>(
        p_W2, w_qkv, p_W3, nullptr,
        256, 256, 512, 512, 256, 256,
        1, (long)256 * 512, 0L, 0L, 0L, (long)256 * 256, 0L);

    // 8) W3 -> fp16
    cvt_hi_kernel<<<1024, t>>>(p_W3, p_W3hi, NB * 256 * 256 / 4);

    // 9) K5: y[b] = W3[b] @ x[b] + b_out
    mma_gemm_big<0><<<dim3(NTILES_K1, 2, NB), t, SMEM_BIG>>>(
        p_W3hi, p_xThi,
        y, nullptr, nullptr, nullptr, b_out,
        256, 256, 256, NPIX,
        256L * 256, (long)NPIX * CDIM, (long)CDIM * NPIX);
}

// round 8
// speedup vs baseline: 1.0563x; 1.0563x over previous
#include <cuda_runtime.h>
#include <cuda_fp16.h>
#include <math_constants.h>
#include <cstdint>

#define NB    16
#define CDIM  256
#define NPIX  4096
#define SPLITK 4
#define NROWS (NB * 512)          // 8192 k rows
#define NTILES_K1 32              // NPIX / 128

// ---------------------------------------------------------------------------
// scratch (device globals; allocation-free per harness rules)
// ---------------------------------------------------------------------------
__device__ __align__(16) __half g_xThi[(size_t)NB * NPIX * CDIM];   // xT[b][n][c] fp16
__device__ __align__(16) __half g_vhi [(size_t)NB * 512 * NPIX];
__device__ __align__(16) __half g_ekhi[(size_t)NB * 512 * NPIX];    // exp(k), no max shift
__device__ float g_partsum[(size_t)NTILES_K1 * NROWS];              // per-ntile row sums
__device__ __align__(16) float g_part[(size_t)SPLITK * 64 * 128 * 128]; // [sp][bh][e][d]
__device__ __align__(16) float g_W2[NB * 256 * 512];
__device__ __align__(16) __half g_wkvhi[1024 * 256];
__device__ __align__(16) __half g_W3hi[NB * 256 * 256];

// ---------------------------------------------------------------------------
// helpers
// ---------------------------------------------------------------------------
__device__ __forceinline__ uint32_t smem_to_u32(const void* p) {
    uint32_t a;
    asm("{ .reg .u64 t; cvta.to.shared.u64 t, %1; cvt.u32.u64 %0, t; }" : "=r"(a) : "l"(p));
    return a;
}

#define LDMATRIX_X4(r, addr) \
    asm volatile("ldmatrix.sync.aligned.m8n8.x4.shared.b16 {%0,%1,%2,%3}, [%4];" \
        : "=r"((r)[0]), "=r"((r)[1]), "=r"((r)[2]), "=r"((r)[3]) : "r"(addr))

#define MMA_F16(d, a, b) \
    asm volatile("mma.sync.aligned.m16n8k16.row.col.f32.f16.f16.f32 " \
        "{%0,%1,%2,%3},{%4,%5,%6,%7},{%8,%9},{%0,%1,%2,%3};" \
        : "+f"((d)[0]), "+f"((d)[1]), "+f"((d)[2]), "+f"((d)[3]) \
        : "r"((a)[0]), "r"((a)[1]), "r"((a)[2]), "r"((a)[3]), \
          "r"((b)[0]), "r"((b)[1]))

#define CP_ASYNC16(saddr, gaddr) \
    asm volatile("cp.async.cg.shared.global [%0], [%1], 16;" :: "r"(saddr), "l"(gaddr))
#define CP_COMMIT()  asm volatile("cp.async.commit_group;")
#define CP_WAIT1()   asm volatile("cp.async.wait_group 1;")
#define CP_WAIT0()   asm volatile("cp.async.wait_group 0;")

// ---------------------------------------------------------------------------
// gmem -> smem stage loader: 2 tiles (A, B), each 128 rows x 64 fp16
// SW128-swizzled 128B rows; tile = 16KB, stage = 32KB, 2 stages.
// ---------------------------------------------------------------------------
__device__ __forceinline__ void load_stage(
    const __half* const* gt, const int* lds,
    uint32_t sb, int tid, int st, int kb)
{
    uint32_t base = sb + st * 32768;
    #pragma unroll
    for (int t = 0; t < 8; t++) {
        int i = tid + t * 256;
        int tile = i >> 10, idx = i & 1023, row = idx >> 3, seg = idx & 7;
        const __half* g = gt[tile] + (size_t)row * lds[tile] + kb + seg * 8;
        uint32_t off = (row << 7) + (seg << 4);
        off ^= (row & 7) << 4;
        CP_ASYNC16(base + tile * 16384 + off, g);
    }
    CP_COMMIT();
}

// ---------------------------------------------------------------------------
// fp16 GEMM via mma.sync: D[128,128] = A[128,K] x B[128,K]^T  (fp32 accum)
// R5-proven configuration: 2-stage, 128x128, 8 warps (4x2), warp 32x64.
// OUTMODE 0: fp32 out (+ optional bias).
// OUTMODE 1 (K1): m0<512 -> ek = exp(acc) as fp16 + per-row partial sums;
//                 m0>=512 -> v as fp16.
// ---------------------------------------------------------------------------
template <int OUTMODE>
__global__ __launch_bounds__(256, 2) void mma_gemm(
    const __half* __restrict__ A, const __half* __restrict__ B,
    float* __restrict__ C, __half* __restrict__ Cek, __half* __restrict__ Cv,
    float* __restrict__ partsum, const float* __restrict__ bias,
    int Ksub, int lda, int ldb, int ldc,
    long sAz, long sBz, long sCz, int ksplit_mode, long sCsplit)
{
    extern __shared__ __align__(128) char smem[];
    uint32_t sb = smem_to_u32(smem);
    const int tid = threadIdx.x, lane = tid & 31, wid = tid >> 5;
    const int wm = wid >> 1, wn = wid & 1;

    int ntile, koff; long coff;
    if (ksplit_mode) { ntile = 0; koff = blockIdx.x * Ksub; coff = (long)blockIdx.x * sCsplit; }
    else             { ntile = blockIdx.x; koff = 0; coff = 0; }
    const int m0 = blockIdx.y * 128;
    const int z  = blockIdx.z;

    const __half* gt[2];
    gt[0] = A + z * sAz + (long)m0 * lda + koff;
    gt[1] = B + z * sBz + (long)ntile * 128 * ldb + koff;
    int lds[2] = { lda, ldb };

    float acc[2][8][4];
    #pragma unroll
    for (int i = 0; i < 2; i++)
        #pragma unroll
        for (int j = 0; j < 8; j++)
            #pragma unroll
            for (int q = 0; q < 4; q++) acc[i][j][q] = 0.0f;

    const int nch = Ksub >> 6;
    load_stage(gt, lds, sb, tid, 0, 0);

    for (int c = 0; c < nch; c++) {
        const int st = c & 1;
        if (c + 1 < nch) { load_stage(gt, lds, sb, tid, st ^ 1, (c + 1) << 6); CP_WAIT1(); }
        else             { CP_WAIT0(); }
        __syncthreads();

        const uint32_t sA = sb + st * 32768;

        #pragma unroll
        for (int s = 0; s < 4; s++) {
            uint32_t ah[2][4];
            #pragma unroll
            for (int mt = 0; mt < 2; mt++) {
                int row = wm * 32 + mt * 16 + (lane & 15);
                uint32_t off = (row << 7) + s * 32 + ((lane >> 4) << 4);
                off ^= (row & 7) << 4;
                LDMATRIX_X4(ah[mt], sA + off);
            }
            uint32_t bh[4][4];
            #pragma unroll
            for (int np = 0; np < 4; np++) {
                int nrow = wn * 64 + np * 16 + ((lane >> 4) << 3) + (lane & 7);
                uint32_t off = (nrow << 7) + s * 32 + (((lane >> 3) & 1) << 4);
                off ^= (nrow & 7) << 4;
                LDMATRIX_X4(bh[np], sA + 16384 + off);
            }
            #pragma unroll
            for (int mt = 0; mt < 2; mt++)
                #pragma unroll
                for (int nt = 0; nt < 8; nt++)
                    MMA_F16(acc[mt][nt], ah[mt], &bh[nt >> 1][(nt & 1) * 2]);
        }
        __syncthreads();
    }

    // -------- epilogue --------
    const int rbase = wm * 32 + (lane >> 2);
    const int cbase = wn * 64 + (lane & 3) * 2;

    if (OUTMODE == 0) {
        float* Cw = C + z * sCz + coff + (long)m0 * ldc + (long)ntile * 128;
        #pragma unroll
        for (int mt = 0; mt < 2; mt++)
            #pragma unroll
            for (int nt = 0; nt < 8; nt++)
                #pragma unroll
                for (int hh = 0; hh < 2; hh++) {
                    int row = rbase + mt * 16 + hh * 8;
                    int col = cbase + nt * 8;
                    float v0 = acc[mt][nt][hh * 2 + 0];
                    float v1 = acc[mt][nt][hh * 2 + 1];
                    if (bias) { float bv = bias[m0 + row]; v0 += bv; v1 += bv; }
                    *(float2*)&Cw[(long)row * ldc + col] = make_float2(v0, v1);
                }
    } else if (m0 < 512) {
        // k rows: exp (no max shift; k ~ N(0,1), fp16 range safe),
        // store fp16, accumulate per-row sums -> deterministic partsum write
        __half* ek = Cek + (long)z * sCz + (long)m0 * ldc + (long)ntile * 128;
        float rs[2][2] = {{0.f, 0.f}, {0.f, 0.f}};
        #pragma unroll
        for (int mt = 0; mt < 2; mt++)
            #pragma unroll
            for (int nt = 0; nt < 8; nt++)
                #pragma unroll
                for (int hh = 0; hh < 2; hh++) {
                    int row = rbase + mt * 16 + hh * 8;
                    int col = cbase + nt * 8;
                    float e0 = __expf(acc[mt][nt][hh * 2 + 0]);
                    float e1 = __expf(acc[mt][nt][hh * 2 + 1]);
                    __half2 p; p.x = __float2half_rn(e0); p.y = __float2half_rn(e1);
                    *(__half2*)&ek[(long)row * ldc + col] = p;
                    rs[mt][hh] += e0 + e1;
                }
        float* red = (float*)smem;   // reuse stage smem (MMA loop fully drained)
        #pragma unroll
        for (int mt = 0; mt < 2; mt++)
            #pragma unroll
            for (int hh = 0; hh < 2; hh++) {
                float v = rs[mt][hh];
                v += __shfl_xor_sync(0xffffffffu, v, 1);
                v += __shfl_xor_sync(0xffffffffu, v, 2);
                if ((lane & 3) == 0)
                    red[wn * 128 + wm * 32 + mt * 16 + hh * 8 + (lane >> 2)] = v;
            }
        __syncthreads();
        if (tid < 128)
            partsum[(long)ntile * NROWS + (long)z * 512 + m0 + tid] = red[tid] + red[128 + tid];
    } else {
        // v rows: fp16 store
        __half* vout = Cv + (long)z * sCz + (long)(m0 - 512) * ldc + (long)ntile * 128;
        #pragma unroll
        for (int mt = 0; mt < 2; mt++)
            #pragma unroll
            for (int nt = 0; nt < 8; nt++)
                #pragma unroll
                for (int hh = 0; hh < 2; hh++) {
                    int row = rbase + mt * 16 + hh * 8;
                    int col = cbase + nt * 8;
                    __half2 p;
                    p.x = __float2half_rn(acc[mt][nt][hh * 2 + 0]);
                    p.y = __float2half_rn(acc[mt][nt][hh * 2 + 1]);
                    *(__half2*)&vout[(long)row * ldc + col] = p;
                }
    }
}

// ---------------------------------------------------------------------------
// x[b][c][n] -> xT[b][n][c] as fp16
// ---------------------------------------------------------------------------
__global__ __launch_bounds__(256) void transpose_kernel(const float* __restrict__ x)
{
    __shared__ float t[32][33];
    int b = blockIdx.z, c0 = blockIdx.y * 32, n0 = blockIdx.x * 32;
    const float* xp = x + ((size_t)b * CDIM + c0) * NPIX + n0;
    int cn = threadIdx.x & 31, rr = threadIdx.x >> 5;
    #pragma unroll
    for (int i = 0; i < 4; i++) {
        int c = rr + i * 8;
        t[c][cn] = xp[(size_t)c * NPIX + cn];
    }
    __syncthreads();
    size_t ob = ((size_t)b * NPIX + n0) * CDIM + c0;
    #pragma unroll
    for (int i = 0; i < 4; i++) {
        int n = rr + i * 8;
        g_xThi[ob + (size_t)n * CDIM + cn] = __float2half_rn(t[cn][n]);
    }
}

// fp32 -> fp16, vectorized (n4 = count/4)
__global__ __launch_bounds__(256) void cvt_hi_kernel(
    const float* __restrict__ src, __half* __restrict__ hi, int n4)
{
    int i = blockIdx.x * 256 + threadIdx.x;
    if (i >= n4) return;
    float4 v = ((const float4*)src)[i];
    __half2 a, b;
    a.x = __float2half_rn(v.x); a.y = __float2half_rn(v.y);
    b.x = __float2half_rn(v.z); b.y = __float2half_rn(v.w);
    ((__half2*)hi)[i * 2 + 0] = a;
    ((__half2*)hi)[i * 2 + 1] = b;
}

// ---------------------------------------------------------------------------
// w2_kernel (fused ctx_reduce + K4a):
//   W2[b][o][h*128+d] = sum_e w_out[o][h*128+e] * ctxN[e][d]
// where ctxN[e][d] = (sum_sp part[sp][bh][e][d]) / den[d],
//       den[d]     = sum_{nt} partsum[nt][b*512+h*128+d]   (fixed order)
// grid (2, 64): x = M-block (bm), y = bh. 256 threads, 8x8 microtile.
// ---------------------------------------------------------------------------
__global__ __launch_bounds__(256) void w2_kernel(const float* __restrict__ w_out)
{
    __shared__ float rden[128];
    __shared__ float As[16][128];
    __shared__ float Bs[16][128];

    const int bh = blockIdx.y;
    const int bm = blockIdx.x * 128;
    const int b = bh >> 2, h = bh & 3;
    const int tid = threadIdx.x;

    if (tid < 128) {
        float s = 0.0f;
        #pragma unroll
        for (int nt = 0; nt < NTILES_K1; nt++)
            s += g_partsum[(long)nt * NROWS + b * 512 + h * 128 + tid];
        rden[tid] = 1.0f / s;
    }
    __syncthreads();

    const int arow = tid >> 2, acol = (tid & 3) * 4;
    const int brow = tid >> 5, bcol = (tid & 31) * 4;
    const int trow = (tid >> 4) * 8, tcol = (tid & 15) * 8;

    float acc[8][8];
    #pragma unroll
    for (int i = 0; i < 8; i++)
        #pragma unroll
        for (int j = 0; j < 8; j++) acc[i][j] = 0.0f;

    const float* pbase = g_part + (size_t)bh * 16384;

    for (int k0 = 0; k0 < 128; k0 += 16) {
        // A chunk: w_out rows bm..bm+128, cols h*128 + k0..k0+16
        #pragma unroll
        for (int i = 0; i < 2; i++) {
            int r = arow + i * 64;
            float4 a = *(const float4*)&w_out[(size_t)(bm + r) * 512 + h * 128 + k0 + acol];
            As[acol + 0][r] = a.x; As[acol + 1][r] = a.y;
            As[acol + 2][r] = a.z; As[acol + 3][r] = a.w;
        }
        // B chunk: Bs[e'][d] = (sum_sp part[sp][bh][k0+e'][d]) * rden[d]
        #pragma unroll
        for (int i = 0; i < 2; i++) {
            int e = brow + i * 8;
            const float* pp = pbase + (size_t)(k0 + e) * 128 + bcol;
            float4 s = make_float4(0.f, 0.f, 0.f, 0.f);
            #pragma unroll
            for (int sp = 0; sp < SPLITK; sp++) {
                float4 v = *(const float4*)(pp + (size_t)sp * 64 * 16384);
                s.x += v.x; s.y += v.y; s.z += v.z; s.w += v.w;
            }
            Bs[e][bcol + 0] = s.x * rden[bcol + 0];
            Bs[e][bcol + 1] = s.y * rden[bcol + 1];
            Bs[e][bcol + 2] = s.z * rden[bcol + 2];
            Bs[e][bcol + 3] = s.w * rden[bcol + 3];
        }
        __syncthreads();
        #pragma unroll
        for (int kk = 0; kk < 16; kk++) {
            float ra[8], rb[8];
            #pragma unroll
            for (int i = 0; i < 8; i++) ra[i] = As[kk][trow + i];
            #pragma unroll
            for (int j = 0; j < 8; j++) rb[j] = Bs[kk][tcol + j];
            #pragma unroll
            for (int i = 0; i < 8; i++)
                #pragma unroll
                for (int j = 0; j < 8; j++) acc[i][j] += ra[i] * rb[j];
        }
        __syncthreads();
    }

    float* C = g_W2 + (size_t)b * 256 * 512 + (size_t)h * 128;
    #pragma unroll
    for (int i = 0; i < 8; i++) {
        int o = bm + trow + i;
        #pragma unroll
        for (int j = 0; j < 8; j += 4)
            *(float4*)&C[(size_t)o * 512 + tcol + j] =
                make_float4(acc[i][j], acc[i][j+1], acc[i][j+2], acc[i][j+3]);
    }
}

// ---------------------------------------------------------------------------
// small SIMT SGEMM (K4b only): C = A @ B, fp16 output
// ---------------------------------------------------------------------------
__global__ __launch_bounds__(256) void sgemm_nn_h(
    const float* __restrict__ A, const float* __restrict__ B,
    __half* __restrict__ Ch,
    int K, int lda, int ldb, int ldc,
    long sAb, long sCb)
{
    __shared__ float As[16][128];
    __shared__ float Bs[16][128];

    int z = blockIdx.z;
    A += z * sAb;
    Ch += z * sCb;

    int tid = threadIdx.x;
    int bm = blockIdx.y * 128;
    int bn = blockIdx.x * 128;

    int arow = tid >> 2, acol = (tid & 3) * 4;
    int brow = tid >> 5, bcol = (tid & 31) * 4;
    int trow = (tid >> 4) * 8, tcol = (tid & 15) * 8;

    float acc[8][8];
    #pragma unroll
    for (int i = 0; i < 8; i++)
        #pragma unroll
        for (int j = 0; j < 8; j++) acc[i][j] = 0.0f;

    for (int k0 = 0; k0 < K; k0 += 16) {
        #pragma unroll
        for (int i = 0; i < 2; i++) {
            int r = arow + i * 64;
            float4 a = *(const float4*)&A[(long)(bm + r) * lda + k0 + acol];
            As[acol + 0][r] = a.x; As[acol + 1][r] = a.y;
            As[acol + 2][r] = a.z; As[acol + 3][r] = a.w;
        }
        #pragma unroll
        for (int i = 0; i < 2; i++) {
            int r = brow + i * 8;
            *(float4*)&Bs[r][bcol] = *(const float4*)&B[(long)(k0 + r) * ldb + bn + bcol];
        }
        __syncthreads();
        #pragma unroll
        for (int kk = 0; kk < 16; kk++) {
            float ra[8], rb[8];
            #pragma unroll
            for (int i = 0; i < 8; i++) ra[i] = As[kk][trow + i];
            #pragma unroll
            for (int j = 0; j < 8; j++) rb[j] = Bs[kk][tcol + j];
            #pragma unroll
            for (int i = 0; i < 8; i++)
                #pragma unroll
                for (int j = 0; j < 8; j++) acc[i][j] += ra[i] * rb[j];
        }
        __syncthreads();
    }

    #pragma unroll
    for (int i = 0; i < 8; i++) {
        long r = bm + trow + i;
        #pragma unroll
        for (int j = 0; j < 8; j += 2) {
            __half2 p;
            p.x = __float2half_rn(acc[i][j + 0]);
            p.y = __float2half_rn(acc[i][j + 1]);
            *(__half2*)&Ch[r * ldc + bn + tcol + j] = p;
        }
    }
}

// ---------------------------------------------------------------------------
extern "C" void kernel_launch(void* const* d_in, const int* in_sizes, int n_in,
                              void* d_out, int out_size)
{
    const float* x     = (const float*)d_in[0];
    const float* w_qkv = (const float*)d_in[1];
    const float* w_out = (const float*)d_in[2];
    const float* b_out = (const float*)d_in[3];
    float* y = (float*)d_out;

    float *p_part, *p_W2, *p_partsum;
    __half *p_xThi, *p_vhi, *p_ekhi, *p_wkvhi, *p_W3hi;
    cudaGetSymbolAddress((void**)&p_part, g_part);
    cudaGetSymbolAddress((void**)&p_W2, g_W2);
    cudaGetSymbolAddress((void**)&p_partsum, g_partsum);
    cudaGetSymbolAddress((void**)&p_xThi, g_xThi);
    cudaGetSymbolAddress((void**)&p_vhi, g_vhi);
    cudaGetSymbolAddress((void**)&p_ekhi, g_ekhi);
    cudaGetSymbolAddress((void**)&p_wkvhi, g_wkvhi);
    cudaGetSymbolAddress((void**)&p_W3hi, g_W3hi);

    const int SMEM_GEMM = 2 * 32768;   // 64 KB, 2 stages (R5 config)
    cudaFuncSetAttribute(mma_gemm<0>, cudaFuncAttributeMaxDynamicSharedMemorySize, SMEM_GEMM);
    cudaFuncSetAttribute(mma_gemm<1>, cudaFuncAttributeMaxDynamicSharedMemorySize, SMEM_GEMM);

    dim3 t(256);

    // 1) x -> xT (fp16)
    transpose_kernel<<<dim3(NPIX / 32, CDIM / 32, NB), t>>>(x);

    // 2) Wkv -> fp16  (rows 512..1535 of w_qkv)
    cvt_hi_kernel<<<256, t>>>(w_qkv + 512 * 256, p_wkvhi, 1024 * 256 / 4);

    // 3) K1: kv = Wkv @ x; epilogue: ek = exp(k) fp16 + row partial sums, v fp16
    mma_gemm<1><<<dim3(NTILES_K1, 8, NB), t, SMEM_GEMM>>>(
        p_wkvhi, p_xThi,
        nullptr, p_ekhi, p_vhi, p_partsum, nullptr,
        256, 256, 256, NPIX,
        0L, (long)NPIX * CDIM, 512L * NPIX, 0, 0L);

    // 4) K3: ctx partials (split-K over n), operands swapped (A=v, B=ek)
    //    -> part[sp][bh][e][d]  (e = v-row, d = ek-row)
    mma_gemm<0><<<dim3(SPLITK, 1, 64), t, SMEM_GEMM>>>(
        p_vhi, p_ekhi,
        p_part, nullptr, nullptr, nullptr, nullptr,
        NPIX / SPLITK, NPIX, NPIX, 128,
        128L * NPIX, 128L * NPIX, 16384L, 1, 64L * 16384);

    // 5) fused: reduce partials + normalize + W2 = w_out_h @ ctxN
    w2_kernel<<<dim3(2, 64), t>>>(w_out);

    // 6) K4b: W3[b] = W2[b] @ Wq  (fp16 output, no separate cvt)
    sgemm_nn_h<<<dim3(2, 2, NB), t>>>(
        p_W2, w_qkv, p_W3hi,
        512, 512, 256, 256,
        (long)256 * 512, (long)256 * 256);

    // 7) K5: y[b] = W3[b] @ x[b] + b_out
    mma_gemm<0><<<dim3(32, 2, NB), t, SMEM_GEMM>>>(
        p_W3hi, p_xThi,
        y, nullptr, nullptr, nullptr, b_out,
        256, 256, 256, NPIX,
        256L * 256, (long)NPIX * CDIM, (long)CDIM * NPIX, 0, 0L);
}

// round 9
// speedup vs baseline: 1.4427x; 1.3658x over previous
#include <cuda_runtime.h>
#include <cuda_fp16.h>
#include <math_constants.h>
#include <cstdint>

#define NB    16
#define CDIM  256
#define NPIX  4096
#define SPLITK 4
#define NROWS (NB * 512)          // 8192 k rows
#define NTILES_K1 32              // NPIX / 128

// ---------------------------------------------------------------------------
// scratch (device globals; allocation-free per harness rules)
// ---------------------------------------------------------------------------
__device__ __align__(16) __half g_xThi[(size_t)NB * NPIX * CDIM];   // xT[b][n][c] fp16
__device__ __align__(16) __half g_vhi [(size_t)NB * 512 * NPIX];
__device__ __align__(16) __half g_ekhi[(size_t)NB * 512 * NPIX];    // exp(k), no max shift
__device__ float g_partsum[(size_t)NTILES_K1 * NROWS];              // per-ntile row sums
__device__ __align__(16) float g_part[(size_t)SPLITK * 64 * 128 * 128]; // [sp][bh][d][e]
__device__ __align__(16) __half g_ctxNh[(size_t)64 * 128 * 128];    // normalized ctx [bh][d][e] fp16
__device__ __align__(16) __half g_W2h[NB * 256 * 512];
__device__ __align__(16) __half g_W3h[NB * 256 * 256];
__device__ __align__(16) __half g_wkvhi[1024 * 256];
__device__ __align__(16) __half g_wouth[256 * 512];
__device__ __align__(16) __half g_wqTh[256 * 512];                  // Wq^T [c][j] fp16

// ---------------------------------------------------------------------------
// helpers
// ---------------------------------------------------------------------------
__device__ __forceinline__ uint32_t smem_to_u32(const void* p) {
    uint32_t a;
    asm("{ .reg .u64 t; cvta.to.shared.u64 t, %1; cvt.u32.u64 %0, t; }" : "=r"(a) : "l"(p));
    return a;
}

#define LDMATRIX_X4(r, addr) \
    asm volatile("ldmatrix.sync.aligned.m8n8.x4.shared.b16 {%0,%1,%2,%3}, [%4];" \
        : "=r"((r)[0]), "=r"((r)[1]), "=r"((r)[2]), "=r"((r)[3]) : "r"(addr))

#define MMA_F16(d, a, b) \
    asm volatile("mma.sync.aligned.m16n8k16.row.col.f32.f16.f16.f32 " \
        "{%0,%1,%2,%3},{%4,%5,%6,%7},{%8,%9},{%0,%1,%2,%3};" \
        : "+f"((d)[0]), "+f"((d)[1]), "+f"((d)[2]), "+f"((d)[3]) \
        : "r"((a)[0]), "r"((a)[1]), "r"((a)[2]), "r"((a)[3]), \
          "r"((b)[0]), "r"((b)[1]))

#define CP_ASYNC16(saddr, gaddr) \
    asm volatile("cp.async.cg.shared.global [%0], [%1], 16;" :: "r"(saddr), "l"(gaddr))
#define CP_COMMIT()  asm volatile("cp.async.commit_group;")
#define CP_WAIT1()   asm volatile("cp.async.wait_group 1;")
#define CP_WAIT0()   asm volatile("cp.async.wait_group 0;")

// ---------------------------------------------------------------------------
// gmem -> smem stage loader: 2 tiles (A, B), each 128 rows x 64 fp16
// SW128-swizzled 128B rows; tile = 16KB, stage = 32KB, 2 stages.
// ---------------------------------------------------------------------------
__device__ __forceinline__ void load_stage(
    const __half* const* gt, const int* lds,
    uint32_t sb, int tid, int st, int kb)
{
    uint32_t base = sb + st * 32768;
    #pragma unroll
    for (int t = 0; t < 8; t++) {
        int i = tid + t * 256;
        int tile = i >> 10, idx = i & 1023, row = idx >> 3, seg = idx & 7;
        const __half* g = gt[tile] + (size_t)row * lds[tile] + kb + seg * 8;
        uint32_t off = (row << 7) + (seg << 4);
        off ^= (row & 7) << 4;
        CP_ASYNC16(base + tile * 16384 + off, g);
    }
    CP_COMMIT();
}

// ---------------------------------------------------------------------------
// fp16 GEMM via mma.sync: D[128,128] = A[128,K] x B[128,K]^T  (fp32 accum)
// R5-proven mainloop: 2-stage, 128x128, 8 warps (4x2), warp 32x64.
// z split: zb = z / zdiv, zh = z % zdiv; operand base += zb*s?b + zh*s?h.
// OUTMODE 0: fp32 out (+ optional bias).
// OUTMODE 1 (K1): m0<512 -> ek = exp(acc) fp16 + per-row partial sums;
//                 m0>=512 -> v fp16.
// OUTMODE 2: fp16 out (to Ch).
// ---------------------------------------------------------------------------
template <int OUTMODE>
__global__ __launch_bounds__(256, 2) void mma_gemm(
    const __half* __restrict__ A, const __half* __restrict__ B,
    float* __restrict__ C, __half* __restrict__ Ch, __half* __restrict__ Cv,
    float* __restrict__ partsum, const float* __restrict__ bias,
    int Ksub, int lda, int ldb, int ldc, int zdiv,
    long sAb, long sAh, long sBb, long sBh, long sCb, long sCh,
    int ksplit_mode, long sCsplit)
{
    extern __shared__ __align__(128) char smem[];
    uint32_t sb = smem_to_u32(smem);
    const int tid = threadIdx.x, lane = tid & 31, wid = tid >> 5;
    const int wm = wid >> 1, wn = wid & 1;

    int ntile, koff; long coff;
    if (ksplit_mode) { ntile = 0; koff = blockIdx.x * Ksub; coff = (long)blockIdx.x * sCsplit; }
    else             { ntile = blockIdx.x; koff = 0; coff = 0; }
    const int m0 = blockIdx.y * 128;
    const int z  = blockIdx.z;
    const int zb = z / zdiv, zh = z - zb * zdiv;
    const long zoffC = zb * sCb + zh * sCh;

    const __half* gt[2];
    gt[0] = A + zb * sAb + zh * sAh + (long)m0 * lda + koff;
    gt[1] = B + zb * sBb + zh * sBh + (long)ntile * 128 * ldb + koff;
    int lds[2] = { lda, ldb };

    float acc[2][8][4];
    #pragma unroll
    for (int i = 0; i < 2; i++)
        #pragma unroll
        for (int j = 0; j < 8; j++)
            #pragma unroll
            for (int q = 0; q < 4; q++) acc[i][j][q] = 0.0f;

    const int nch = Ksub >> 6;
    load_stage(gt, lds, sb, tid, 0, 0);

    for (int c = 0; c < nch; c++) {
        const int st = c & 1;
        if (c + 1 < nch) { load_stage(gt, lds, sb, tid, st ^ 1, (c + 1) << 6); CP_WAIT1(); }
        else             { CP_WAIT0(); }
        __syncthreads();

        const uint32_t sA = sb + st * 32768;

        #pragma unroll
        for (int s = 0; s < 4; s++) {
            uint32_t ah[2][4];
            #pragma unroll
            for (int mt = 0; mt < 2; mt++) {
                int row = wm * 32 + mt * 16 + (lane & 15);
                uint32_t off = (row << 7) + s * 32 + ((lane >> 4) << 4);
                off ^= (row & 7) << 4;
                LDMATRIX_X4(ah[mt], sA + off);
            }
            uint32_t bh[4][4];
            #pragma unroll
            for (int np = 0; np < 4; np++) {
                int nrow = wn * 64 + np * 16 + ((lane >> 4) << 3) + (lane & 7);
                uint32_t off = (nrow << 7) + s * 32 + (((lane >> 3) & 1) << 4);
                off ^= (nrow & 7) << 4;
                LDMATRIX_X4(bh[np], sA + 16384 + off);
            }
            #pragma unroll
            for (int mt = 0; mt < 2; mt++)
                #pragma unroll
                for (int nt = 0; nt < 8; nt++)
                    MMA_F16(acc[mt][nt], ah[mt], &bh[nt >> 1][(nt & 1) * 2]);
        }
        __syncthreads();
    }

    // -------- epilogue --------
    const int rbase = wm * 32 + (lane >> 2);
    const int cbase = wn * 64 + (lane & 3) * 2;

    if (OUTMODE == 0) {
        float* Cw = C + zoffC + coff + (long)m0 * ldc + (long)ntile * 128;
        #pragma unroll
        for (int mt = 0; mt < 2; mt++)
            #pragma unroll
            for (int nt = 0; nt < 8; nt++)
                #pragma unroll
                for (int hh = 0; hh < 2; hh++) {
                    int row = rbase + mt * 16 + hh * 8;
                    int col = cbase + nt * 8;
                    float v0 = acc[mt][nt][hh * 2 + 0];
                    float v1 = acc[mt][nt][hh * 2 + 1];
                    if (bias) { float bv = bias[m0 + row]; v0 += bv; v1 += bv; }
                    *(float2*)&Cw[(long)row * ldc + col] = make_float2(v0, v1);
                }
    } else if (OUTMODE == 2) {
        __half* Cw = Ch + zoffC + (long)m0 * ldc + (long)ntile * 128;
        #pragma unroll
        for (int mt = 0; mt < 2; mt++)
            #pragma unroll
            for (int nt = 0; nt < 8; nt++)
                #pragma unroll
                for (int hh = 0; hh < 2; hh++) {
                    int row = rbase + mt * 16 + hh * 8;
                    int col = cbase + nt * 8;
                    __half2 p;
                    p.x = __float2half_rn(acc[mt][nt][hh * 2 + 0]);
                    p.y = __float2half_rn(acc[mt][nt][hh * 2 + 1]);
                    *(__half2*)&Cw[(long)row * ldc + col] = p;
                }
    } else if (m0 < 512) {
        // K1 k rows: exp (no max shift; k ~ N(0,1), fp16 range safe),
        // store fp16, accumulate per-row sums -> deterministic partsum write
        __half* ek = Ch + zoffC + (long)m0 * ldc + (long)ntile * 128;
        float rs[2][2] = {{0.f, 0.f}, {0.f, 0.f}};
        #pragma unroll
        for (int mt = 0; mt < 2; mt++)
            #pragma unroll
            for (int nt = 0; nt < 8; nt++)
                #pragma unroll
                for (int hh = 0; hh < 2; hh++) {
                    int row = rbase + mt * 16 + hh * 8;
                    int col = cbase + nt * 8;
                    float e0 = __expf(acc[mt][nt][hh * 2 + 0]);
                    float e1 = __expf(acc[mt][nt][hh * 2 + 1]);
                    __half2 p; p.x = __float2half_rn(e0); p.y = __float2half_rn(e1);
                    *(__half2*)&ek[(long)row * ldc + col] = p;
                    rs[mt][hh] += e0 + e1;
                }
        float* red = (float*)smem;   // reuse stage smem (MMA loop fully drained)
        #pragma unroll
        for (int mt = 0; mt < 2; mt++)
            #pragma unroll
            for (int hh = 0; hh < 2; hh++) {
                float v = rs[mt][hh];
                v += __shfl_xor_sync(0xffffffffu, v, 1);
                v += __shfl_xor_sync(0xffffffffu, v, 2);
                if ((lane & 3) == 0)
                    red[wn * 128 + wm * 32 + mt * 16 + hh * 8 + (lane >> 2)] = v;
            }
        __syncthreads();
        if (tid < 128)
            partsum[(long)ntile * NROWS + (long)z * 512 + m0 + tid] = red[tid] + red[128 + tid];
    } else {
        // K1 v rows: fp16 store
        __half* vout = Cv + zoffC + (long)(m0 - 512) * ldc + (long)ntile * 128;
        #pragma unroll
        for (int mt = 0; mt < 2; mt++)
            #pragma unroll
            for (int nt = 0; nt < 8; nt++)
                #pragma unroll
                for (int hh = 0; hh < 2; hh++) {
                    int row = rbase + mt * 16 + hh * 8;
                    int col = cbase + nt * 8;
                    __half2 p;
                    p.x = __float2half_rn(acc[mt][nt][hh * 2 + 0]);
                    p.y = __float2half_rn(acc[mt][nt][hh * 2 + 1]);
                    *(__half2*)&vout[(long)row * ldc + col] = p;
                }
    }
}

// ---------------------------------------------------------------------------
// x[b][c][n] -> xT[b][n][c] fp16. Tile 64c x 32n, float4 reads, half2 writes.
// ---------------------------------------------------------------------------
__global__ __launch_bounds__(256) void transpose_kernel(const float* __restrict__ x)
{
    __shared__ float t[64][33];
    int b = blockIdx.z, c0 = blockIdx.y * 64, n0 = blockIdx.x * 32;
    const float* xp = x + ((size_t)b * CDIM + c0) * NPIX + n0;
    int tid = threadIdx.x;

    int rr = tid >> 3, col4 = (tid & 7) * 4;
    #pragma unroll
    for (int p = 0; p < 2; p++) {
        int c = rr + p * 32;
        float4 v = *(const float4*)&xp[(size_t)c * NPIX + col4];
        t[c][col4 + 0] = v.x; t[c][col4 + 1] = v.y;
        t[c][col4 + 2] = v.z; t[c][col4 + 3] = v.w;
    }
    __syncthreads();

    size_t ob = ((size_t)b * NPIX + n0) * CDIM + c0;
    int nloc = tid >> 5, cp = (tid & 31) * 2;
    #pragma unroll
    for (int p = 0; p < 4; p++) {
        int n = nloc + p * 8;
        __half2 h;
        h.x = __float2half_rn(t[cp + 0][n]);
        h.y = __float2half_rn(t[cp + 1][n]);
        *(__half2*)&g_xThi[ob + (size_t)n * CDIM + cp] = h;
    }
}

// ---------------------------------------------------------------------------
// weights_prep (single launch):
//   blocks [0,256):   Wkv (w_qkv rows 512..1535) -> fp16
//   blocks [256,384): w_out -> fp16
//   blocks [384,512): Wq (w_qkv rows 0..511) -> WqT fp16 [c][j]
// ---------------------------------------------------------------------------
__global__ __launch_bounds__(256) void weights_prep(
    const float* __restrict__ w_qkv, const float* __restrict__ w_out)
{
    __shared__ float s[32][33];
    int blk = blockIdx.x, tid = threadIdx.x;

    if (blk < 256) {
        int i = blk * 256 + tid;                  // 65536 float4s
        float4 v = ((const float4*)(w_qkv + 512 * 256))[i];
        __half2 a, b;
        a.x = __float2half_rn(v.x); a.y = __float2half_rn(v.y);
        b.x = __float2half_rn(v.z); b.y = __float2half_rn(v.w);
        ((__half2*)g_wkvhi)[i * 2 + 0] = a;
        ((__half2*)g_wkvhi)[i * 2 + 1] = b;
    } else if (blk < 384) {
        int i = (blk - 256) * 256 + tid;          // 32768 float4s
        float4 v = ((const float4*)w_out)[i];
        __half2 a, b;
        a.x = __float2half_rn(v.x); a.y = __float2half_rn(v.y);
        b.x = __float2half_rn(v.z); b.y = __float2half_rn(v.w);
        ((__half2*)g_wouth)[i * 2 + 0] = a;
        ((__half2*)g_wouth)[i * 2 + 1] = b;
    } else {
        int tnum = blk - 384;                     // 128 tiles: 16 j-tiles x 8 c-tiles
        int j0 = (tnum >> 3) * 32, c0 = (tnum & 7) * 32;
        int r = tid >> 5, cn = tid & 31;
        #pragma unroll
        for (int p = 0; p < 4; p++)
            s[r + p * 8][cn] = w_qkv[(size_t)(j0 + r + p * 8) * 256 + c0 + cn];
        __syncthreads();
        #pragma unroll
        for (int p = 0; p < 4; p++) {
            int c = r + p * 8;
            g_wqTh[(size_t)(c0 + c) * 512 + j0 + cn] = __float2half_rn(s[cn][c]);
        }
    }
}

// ---------------------------------------------------------------------------
// prep_ctx: ctxNh[bh][d][e] = (sum_sp part[sp][bh][d][e]) / den[d]  as fp16
// den[d] = sum_nt partsum[nt][b*512+h*128+d] (fixed order -> deterministic)
// ---------------------------------------------------------------------------
__global__ __launch_bounds__(256) void prep_ctx()
{
    __shared__ float sden[2];
    int bh = blockIdx.y;
    int b = bh >> 2, h = bh & 3;
    if (threadIdx.x < 2) {
        int d = blockIdx.x * 2 + threadIdx.x;
        int row = b * 512 + h * 128 + d;
        float s = 0.0f;
        #pragma unroll
        for (int nt = 0; nt < NTILES_K1; nt++)
            s += g_partsum[(long)nt * NROWS + row];
        sden[threadIdx.x] = 1.0f / s;
    }
    __syncthreads();

    int idx = blockIdx.x * 256 + threadIdx.x;   // 0..16383, layout [d][e]
    int d = idx >> 7;
    float s = 0.0f;
    #pragma unroll
    for (int sp = 0; sp < SPLITK; sp++)
        s += g_part[((size_t)sp * 64 + bh) * 16384 + idx];
    g_ctxNh[(size_t)bh * 16384 + idx] = __float2half_rn(s * sden[d & 1]);
}

// ---------------------------------------------------------------------------
extern "C" void kernel_launch(void* const* d_in, const int* in_sizes, int n_in,
                              void* d_out, int out_size)
{
    const float* x     = (const float*)d_in[0];
    const float* w_qkv = (const float*)d_in[1];
    const float* w_out = (const float*)d_in[2];
    const float* b_out = (const float*)d_in[3];
    float* y = (float*)d_out;

    float *p_part, *p_partsum;
    __half *p_xThi, *p_vhi, *p_ekhi, *p_wkvhi, *p_wouth, *p_wqTh, *p_ctxNh, *p_W2h, *p_W3h;
    cudaGetSymbolAddress((void**)&p_part, g_part);
    cudaGetSymbolAddress((void**)&p_partsum, g_partsum);
    cudaGetSymbolAddress((void**)&p_xThi, g_xThi);
    cudaGetSymbolAddress((void**)&p_vhi, g_vhi);
    cudaGetSymbolAddress((void**)&p_ekhi, g_ekhi);
    cudaGetSymbolAddress((void**)&p_wkvhi, g_wkvhi);
    cudaGetSymbolAddress((void**)&p_wouth, g_wouth);
    cudaGetSymbolAddress((void**)&p_wqTh, g_wqTh);
    cudaGetSymbolAddress((void**)&p_ctxNh, g_ctxNh);
    cudaGetSymbolAddress((void**)&p_W2h, g_W2h);
    cudaGetSymbolAddress((void**)&p_W3h, g_W3h);

    const int SMEM_GEMM = 2 * 32768;   // 64 KB, 2 stages (R5 config)
    cudaFuncSetAttribute(mma_gemm<0>, cudaFuncAttributeMaxDynamicSharedMemorySize, SMEM_GEMM);
    cudaFuncSetAttribute(mma_gemm<1>, cudaFuncAttributeMaxDynamicSharedMemorySize, SMEM_GEMM);
    cudaFuncSetAttribute(mma_gemm<2>, cudaFuncAttributeMaxDynamicSharedMemorySize, SMEM_GEMM);

    dim3 t(256);

    // 1) weight prep: Wkv fp16, w_out fp16, WqT fp16 (one launch)
    weights_prep<<<512, t>>>(w_qkv, w_out);

    // 2) x -> xT (fp16)
    transpose_kernel<<<dim3(NPIX / 32, CDIM / 64, NB), t>>>(x);

    // 3) K1: kv = Wkv @ x; epilogue: ek = exp(k) fp16 + row partial sums, v fp16
    mma_gemm<1><<<dim3(NTILES_K1, 8, NB), t, SMEM_GEMM>>>(
        p_wkvhi, p_xThi,
        nullptr, p_ekhi, p_vhi, p_partsum, nullptr,
        256, 256, 256, NPIX, 1,
        0L, 0L, (long)NPIX * CDIM, 0L, 512L * NPIX, 0L,
        0, 0L);

    // 4) K3: part[sp][bh][d][e] = ek-chunk @ v-chunk^T (split-K over n)
    mma_gemm<0><<<dim3(SPLITK, 1, 64), t, SMEM_GEMM>>>(
        p_ekhi, p_vhi,
        p_part, nullptr, nullptr, nullptr, nullptr,
        NPIX / SPLITK, NPIX, NPIX, 128, 1,
        128L * NPIX, 0L, 128L * NPIX, 0L, 16384L, 0L,
        1, 64L * 16384);

    // 5) reduce + normalize -> ctxNh fp16
    prep_ctx<<<dim3(64, 64), t>>>();

    // 6) w2 (mma): W2h[b][o][h*128+d] = w_out_h[o, h*128+:] @ ctxNh[bh]^T
    mma_gemm<2><<<dim3(1, 2, 64), t, SMEM_GEMM>>>(
        p_wouth, p_ctxNh,
        nullptr, p_W2h, nullptr, nullptr, nullptr,
        128, 512, 128, 512, 4,
        0L, 128L, 4L * 16384, 16384L, 256L * 512, 128L,
        0, 0L);

    // 7) K4b (mma): W3h[b] = W2h[b] @ WqT^T
    mma_gemm<2><<<dim3(2, 2, NB), t, SMEM_GEMM>>>(
        p_W2h, p_wqTh,
        nullptr, p_W3h, nullptr, nullptr, nullptr,
        512, 512, 512, 256, 1,
        256L * 512, 0L, 0L, 0L, 256L * 256, 0L,
        0, 0L);

    // 8) K5: y[b] = W3[b] @ x[b] + b_out
    mma_gemm<0><<<dim3(32, 2, NB), t, SMEM_GEMM>>>(
        p_W3h, p_xThi,
        y, nullptr, nullptr, nullptr, b_out,
        256, 256, 256, NPIX, 1,
        256L * 256, 0L, (long)NPIX * CDIM, 0L, (long)CDIM * NPIX, 0L,
        0, 0L);
}